// round 10
// baseline (speedup 1.0000x reference)
#include <cuda_runtime.h>
#include <cstdint>

// Problem constants
#define BB   8
#define LL   200
#define DD   128
#define HH   4
#define HS   32
#define HB   (HH*BB)        // 32
#define NROW (HB*LL)        // 6400
#define CAP  204

// Scratch (device globals; no allocation allowed)
__device__ float g_ad[BB*LL*DD];       // a in [b][i][d]
__device__ float g_bd[BB*LL*DD];       // b in [b][j][d]
__device__ float g_sv[HB*LL*HS];       // sv in [bh][j][hs]
__device__ float g_raw[NROW*LL];       // only j<=i valid
__device__ int   g_cnt[NROW];
__device__ int   g_list[NROW*CAP];

// ---------------------------------------------------------------------------
// Stage 1: fused 3-matrix projection.
// grid (50 rowtiles of 32, 12 coltiles of 32 over concatenated N=384),
// block 128 (4 warps/SMSP for latency hiding). Tile 32x32, 2x4 per thread.
// Full-K staged once, XOR-swizzled, conflict-free STS + LDS.
// Accumulation order identical to the R8-passing version (bitwise-same out).
// Also zeroes g_cnt.
// ---------------------------------------------------------------------------
__global__ void __launch_bounds__(128) k_gemm(
                       const float* __restrict__ seqs,
                       const float* __restrict__ w1, const float* __restrict__ b1,
                       const float* __restrict__ w2, const float* __restrict__ b2,
                       const float* __restrict__ w3, const float* __restrict__ b3)
{
    __shared__ float st[128 * 32];   // [k][r swizzled] 16 KB
    __shared__ float wt[128 * 32];   // [k][c swizzled] 16 KB

    const int ct = blockIdx.y;
    const int m  = ct >> 2;                 // matrix 0..2
    const int o0 = (ct & 3) * 32;           // col base within matrix
    const float* w    = (m == 0) ? w1 : (m == 1) ? w2 : w3;
    const float* bias = (m == 0) ? b1 : (m == 1) ? b2 : b3;

    const int row0 = blockIdx.x * 32;
    const int tid  = threadIdx.x;

    {
        int idx = (blockIdx.y * 50 + blockIdx.x) * 128 + tid;
        if (idx < NROW) g_cnt[idx] = 0;
    }

    // Stage seqs tile: lane owns row r = idx&31 -> conflict-free STS.
#pragma unroll
    for (int it = 0; it < 8; it++) {
        int idx = it * 128 + tid;
        int r = idx & 31, k = (idx >> 5) * 4;
        float4 v = *(const float4*)&seqs[(row0 + r) * DD + k];
        st[(k + 0) * 32 + (r ^ (((k + 0) & 7) << 2))] = v.x;
        st[(k + 1) * 32 + (r ^ (((k + 1) & 7) << 2))] = v.y;
        st[(k + 2) * 32 + (r ^ (((k + 2) & 7) << 2))] = v.z;
        st[(k + 3) * 32 + (r ^ (((k + 3) & 7) << 2))] = v.w;
    }
#pragma unroll
    for (int it = 0; it < 8; it++) {
        int idx = it * 128 + tid;
        int c = idx & 31, k = (idx >> 5) * 4;
        float4 v = *(const float4*)&w[(o0 + c) * DD + k];
        wt[(k + 0) * 32 + (c ^ (((k + 0) & 7) << 2))] = v.x;
        wt[(k + 1) * 32 + (c ^ (((k + 1) & 7) << 2))] = v.y;
        wt[(k + 2) * 32 + (c ^ (((k + 2) & 7) << 2))] = v.z;
        wt[(k + 3) * 32 + (c ^ (((k + 3) & 7) << 2))] = v.w;
    }
    __syncthreads();

    const int rg = tid >> 3;       // 0..15
    const int cg = tid & 7;        // 0..7
    const int r0 = rg * 2, c0 = cg * 4;

    float acc[2][4];
#pragma unroll
    for (int r = 0; r < 2; r++)
#pragma unroll
        for (int c = 0; c < 4; c++) acc[r][c] = 0.f;

#pragma unroll 8
    for (int k = 0; k < DD; k++) {
        const int sw = (k & 7) << 2;
        float2 s2 = *(const float2*)&st[k * 32 + (r0 ^ sw)];
        float4 w4 = *(const float4*)&wt[k * 32 + (c0 ^ sw)];
        float sv[2] = {s2.x, s2.y};
        float wv[4] = {w4.x, w4.y, w4.z, w4.w};
#pragma unroll
        for (int r = 0; r < 2; r++)
#pragma unroll
            for (int c = 0; c < 4; c++)
                acc[r][c] += sv[r] * wv[c];
    }

    float bi[4];
#pragma unroll
    for (int c = 0; c < 4; c++) bi[c] = bias[o0 + c0 + c];

    if (m == 2) {
        const int h = o0 >> 5;              // c0+c < 32
#pragma unroll
        for (int r = 0; r < 2; r++) {
            int n = row0 + r0 + r;
            int b_ = n / LL, i = n % LL;
            float4 v = {acc[r][0] + bi[0], acc[r][1] + bi[1],
                        acc[r][2] + bi[2], acc[r][3] + bi[3]};
            *(float4*)&g_sv[((h * BB + b_) * LL + i) * HS + c0] = v;
        }
    } else {
        float* dst = (m == 0) ? g_ad : g_bd;
#pragma unroll
        for (int r = 0; r < 2; r++) {
            int n = row0 + r0 + r;
            float4 v = {acc[r][0] + bi[0], acc[r][1] + bi[1],
                        acc[r][2] + bi[2], acc[r][3] + bi[3]};
            *(float4*)&dst[n * DD + o0 + c0] = v;
        }
    }
}

// ---------------------------------------------------------------------------
// Stage 2 (fused raw + top-k + list push), 4 j-streams per warp iteration.
// Arithmetic per (i,j) is BIT-IDENTICAL to the R8-passing version:
// lane owns 8 channels (sub = lane&15, d0 = 8*sub; head h = sub>>2), partial
// computed as two float4 FMA groups, then xor-1/xor-2 tree over 4 lanes.
// half = lane>>4 picks j parity; streams at +0,+8,+16,+24 (stride 32) give
// 16 LDG.128 in flight and 4 interleaved shfl chains per iteration.
// Writer lanes (lane&3)==0 keep top-3 (ascending-j visits, strict >);
// exact lax.top_k merge (value desc, index asc) + masked-zero candidates;
// then push symmetrized-mask candidate lists via atomics.
// ---------------------------------------------------------------------------
__global__ void k_rawtop(const float* __restrict__ tm)
{
    const int i = blockIdx.x, b = blockIdx.y;
    const int tid = threadIdx.x;
    const int w = tid >> 5, lane = tid & 31;
    const int half = lane >> 4;
    const int sub  = lane & 15;
    const int h    = sub >> 2;
    const int d0   = sub * 8;

    __shared__ float tvs[4][2][HH][3];
    __shared__ int   tjs[4][2][HH][3];

    const float4* ap = (const float4*)(g_ad + (size_t)(b * LL + i) * DD + d0);
    const float4 aA = ap[0], aB = ap[1];
    float an = aA.x*aA.x + aA.y*aA.y + aA.z*aA.z + aA.w*aA.w
             + aB.x*aB.x + aB.y*aB.y + aB.z*aB.z + aB.w*aB.w;
    an += __shfl_xor_sync(0xffffffffu, an, 1);
    an += __shfl_xor_sync(0xffffffffu, an, 2);
    an = sqrtf(an);

    float v0 = -3.4e38f, v1 = -3.4e38f, v2 = -3.4e38f;
    int   j0 = -1, j1 = -1, j2 = -1;

    const float* tmp = tm   + (size_t)(b * LL + i) * LL * DD + d0;
    const float* bp  = g_bd + (size_t)b * LL * DD + d0;
    float* rr = g_raw + (size_t)((h * BB + b) * LL + i) * LL;

    for (int jb = 2 * w; jb <= i; jb += 32) {
        const int jj[4] = {jb + half, jb + 8 + half, jb + 16 + half, jb + 24 + half};
        float num[4], den[4];
        bool  pr[4];

#pragma unroll
        for (int s = 0; s < 4; s++) {
            pr[s] = (jj[s] <= i);
            num[s] = 0.f; den[s] = 0.f;
            if (pr[s]) {
                const float4* t4 = (const float4*)(tmp + (size_t)jj[s] * DD);
                const float4* b4 = (const float4*)(bp  + (size_t)jj[s] * DD);
                float4 t0 = t4[0], t1 = t4[1], c0v = b4[0], c1 = b4[1];
                float sx = t0.x + c0v.x, sy = t0.y + c0v.y, sz = t0.z + c0v.z, sw = t0.w + c0v.w;
                num[s] = aA.x*sx + aA.y*sy + aA.z*sz + aA.w*sw;
                den[s] = sx*sx + sy*sy + sz*sz + sw*sw;
                sx = t1.x + c1.x; sy = t1.y + c1.y; sz = t1.z + c1.z; sw = t1.w + c1.w;
                num[s] += aB.x*sx + aB.y*sy + aB.z*sz + aB.w*sw;
                den[s] += sx*sx + sy*sy + sz*sz + sw*sw;
            }
        }

#pragma unroll
        for (int s = 0; s < 4; s++) {
            num[s] += __shfl_xor_sync(0xffffffffu, num[s], 1);
            den[s] += __shfl_xor_sync(0xffffffffu, den[s], 1);
        }
#pragma unroll
        for (int s = 0; s < 4; s++) {
            num[s] += __shfl_xor_sync(0xffffffffu, num[s], 2);
            den[s] += __shfl_xor_sync(0xffffffffu, den[s], 2);
        }

        if ((lane & 3) == 0) {
#pragma unroll
            for (int s = 0; s < 4; s++) {
                if (pr[s]) {
                    float v = num[s] / (an * sqrtf(den[s]) + 1e-6f);
                    rr[jj[s]] = v;
                    if (v > v0)      { v2=v1; j2=j1; v1=v0; j1=j0; v0=v; j0=jj[s]; }
                    else if (v > v1) { v2=v1; j2=j1; v1=v;  j1=jj[s]; }
                    else if (v > v2) { v2=v;  j2=jj[s]; }
                }
            }
        }
    }

    if ((lane & 3) == 0) {
        tvs[w][half][h][0] = v0; tjs[w][half][h][0] = j0;
        tvs[w][half][h][1] = v1; tjs[w][half][h][1] = j1;
        tvs[w][half][h][2] = v2; tjs[w][half][h][2] = j2;
    }
    __syncthreads();

    // merge + list push: thread hh < 4 handles head hh
    if (tid < HH) {
        const int hh = tid;
        float V0 = -3.4e38f, V1 = -3.4e38f, V2 = -3.4e38f;
        int   I0 = 0x7fffffff, I1 = 0x7fffffff, I2 = 0x7fffffff;
        auto ins = [&](float v, int j) {
            if (j < 0) return;
            if (v > V0 || (v == V0 && j < I0)) { V2=V1;I2=I1; V1=V0;I1=I0; V0=v;I0=j; }
            else if (v > V1 || (v == V1 && j < I1)) { V2=V1;I2=I1; V1=v;I1=j; }
            else if (v > V2 || (v == V2 && j < I2)) { V2=v;I2=j; }
        };
#pragma unroll
        for (int ww = 0; ww < 4; ww++)
#pragma unroll
            for (int hf = 0; hf < 2; hf++)
#pragma unroll
                for (int qq = 0; qq < 3; qq++)
                    ins(tvs[ww][hf][hh][qq], tjs[ww][hf][hh][qq]);
#pragma unroll
        for (int z = 1; z <= 3; z++) {
            int jz = i + z;
            if (jz < LL) ins(0.0f, jz);   // masked zeros (index-asc ties)
        }
        const int bh = hh * BB + b;
        const int rg = bh * LL + i;
        int sel[3] = {I0, I1, I2};
#pragma unroll
        for (int s = 0; s < 3; s++) {
            int t = sel[s];
            if (t <= i) {
                int p = atomicAdd(&g_cnt[rg], 1);
                if (p < CAP) g_list[rg * CAP + p] = t;
            } else {
                int tg = bh * LL + t;
                int p = atomicAdd(&g_cnt[tg], 1);
                if (p < CAP) g_list[tg * CAP + p] = i;
            }
        }
    }
}

// ---------------------------------------------------------------------------
// Stage 3 (fused sparse gather + LayerNorm): block per (b,i), warp = head.
// Bitmask dedup; paired bit extraction for MLP; ascending-j (deterministic).
// ---------------------------------------------------------------------------
__global__ void k_gather_ln(const float* __restrict__ tm,
                            const float* __restrict__ gam,
                            const float* __restrict__ bet,
                            float* __restrict__ out_ln,
                            float* __restrict__ out_tio)
{
    const int i = blockIdx.x, b = blockIdx.y;
    const int tid = threadIdx.x;
    const int h = tid >> 5, lane = tid & 31;
    const int bh = h * BB + b;
    const int rg = bh * LL + i;

    __shared__ unsigned bm[HH][7];
    __shared__ float red[4];

    if (lane < 7) bm[h][lane] = 0u;
    __syncwarp();

    const int n = min(g_cnt[rg], CAP);
    for (int c = lane; c < n; c += 32) {
        int j = g_list[rg * CAP + c];
        atomicOr(&bm[h][j >> 5], 1u << (j & 31));
    }
    __syncwarp();

    float ao = 0.f, at = 0.f;
    float ao2 = 0.f, at2 = 0.f;
    const float* rrow = g_raw + (size_t)rg * LL;
    const float* tmb  = tm + (size_t)(b * LL + i) * LL * DD + h * HS + lane;
    const float* svb  = g_sv + (size_t)bh * LL * HS + lane;

    for (int w = 0; w < 7; w++) {
        unsigned m = bm[h][w];
        while (m) {
            int b1 = __ffs(m) - 1;  m &= m - 1;
            int b2 = -1;
            if (m) { b2 = __ffs(m) - 1; m &= m - 1; }
            int ja = w * 32 + b1;
            float sga = rrow[ja];
            float sv_a = svb[ja * HS];
            float tm_a = tmb[(size_t)ja * DD];
            if (b2 >= 0) {
                int jb2 = w * 32 + b2;
                float sgb = rrow[jb2];
                ao2 += sgb * svb[jb2 * HS];
                at2 += sgb * tmb[(size_t)jb2 * DD];
            }
            ao += sga * sv_a;
            at += sga * tm_a;
        }
    }
    ao += ao2;
    at += at2;

    const int d = tid;                 // d = h*HS + lane
    out_tio[(b * LL + i) * DD + d] = at;

    // LayerNorm over the 128 'ao' values
    float s = ao;
#pragma unroll
    for (int k = 16; k; k >>= 1) s += __shfl_xor_sync(0xffffffffu, s, k);
    if (lane == 0) red[h] = s;
    __syncthreads();
    float mu = (red[0] + red[1] + red[2] + red[3]) * (1.f / 128.f);
    __syncthreads();

    float dv = ao - mu;
    float s2 = dv * dv;
#pragma unroll
    for (int k = 16; k; k >>= 1) s2 += __shfl_xor_sync(0xffffffffu, s2, k);
    if (lane == 0) red[h] = s2;
    __syncthreads();
    float var = (red[0] + red[1] + red[2] + red[3]) * (1.f / 128.f);

    out_ln[(b * LL + i) * DD + d] = dv / sqrtf(var + 1e-8f) * gam[d] + bet[d];
}

// ---------------------------------------------------------------------------
extern "C" void kernel_launch(void* const* d_in, const int* in_sizes, int n_in,
                              void* d_out, int out_size)
{
    const float* seqs = (const float*)d_in[0];
    // d_in[1] = attention_mask (known causal triu) — unused
    const float* tm   = (const float*)d_in[2];
    const float* w1   = (const float*)d_in[3];
    const float* b1   = (const float*)d_in[4];
    const float* w2   = (const float*)d_in[5];
    const float* b2   = (const float*)d_in[6];
    const float* w3   = (const float*)d_in[7];
    const float* b3   = (const float*)d_in[8];
    const float* lng  = (const float*)d_in[9];
    const float* lnb  = (const float*)d_in[10];

    float* out_ln  = (float*)d_out;
    float* out_tio = out_ln + BB * LL * DD;

    k_gemm     <<<dim3(50, 12), 128>>>(seqs, w1, b1, w2, b2, w3, b3);
    k_rawtop   <<<dim3(LL, BB), 128>>>(tm);
    k_gather_ln<<<dim3(LL, BB), 128>>>(tm, lng, lnb, out_ln, out_tio);
}

// round 11
// speedup vs baseline: 1.0885x; 1.0885x over previous
#include <cuda_runtime.h>
#include <cstdint>

// Problem constants
#define BB   8
#define LL   200
#define DD   128
#define HH   4
#define HS   32
#define HB   (HH*BB)        // 32
#define NROW (HB*LL)        // 6400
#define CAP  204

// Scratch (device globals; no allocation allowed)
__device__ float g_ad[BB*LL*DD];       // a in [b][i][d]
__device__ float g_bd[BB*LL*DD];       // b in [b][j][d]
__device__ float g_sv[HB*LL*HS];       // sv in [bh][j][hs]
__device__ float g_raw[NROW*LL];       // only j<=i valid
__device__ int   g_cnt[NROW];
__device__ int   g_list[NROW*CAP];

// ---------------------------------------------------------------------------
// Stage 1: a/b projections only (sv moved into k_rawtop's grid).
// grid (25 rowtiles of 64, 8 coltiles of 32 over concatenated N=256),
// block 64. Tile 64x32, 8x4 per thread: per k, 3 LDS.128 : 32 FFMA
// (0.75x the smem bytes/FFMA of R8). No swizzle needed: compute LDS is
// warp-uniform-k broadcast; staging STS is lane-consecutive.
// Per-output FMA order = serial k (bit-identical to the R8-passing gemm).
// Also zeroes g_cnt.
// ---------------------------------------------------------------------------
__global__ void __launch_bounds__(64) k_gemm(
                       const float* __restrict__ seqs,
                       const float* __restrict__ w1, const float* __restrict__ b1,
                       const float* __restrict__ w2, const float* __restrict__ b2)
{
    __shared__ float st[DD * 64];   // [k][r] 32 KB
    __shared__ float wt[DD * 32];   // [k][c] 16 KB

    const int ct = blockIdx.y;
    const int m  = ct >> 2;                 // matrix 0..1
    const int o0 = (ct & 3) * 32;           // col base within matrix
    const float* w    = (m == 0) ? w1 : w2;
    const float* bias = (m == 0) ? b1 : b2;

    const int row0 = blockIdx.x * 64;
    const int tid  = threadIdx.x;

    {
        int idx = (blockIdx.y * 25 + blockIdx.x) * 64 + tid;
        if (idx < NROW) g_cnt[idx] = 0;
    }

    // Stage seqs tile: lane = row (tid 0..63), sweep k. STS lane-consecutive.
#pragma unroll
    for (int it = 0; it < 32; it++) {
        float4 v = *(const float4*)&seqs[(row0 + tid) * DD + it * 4];
        int k = it * 4;
        st[(k + 0) * 64 + tid] = v.x;
        st[(k + 1) * 64 + tid] = v.y;
        st[(k + 2) * 64 + tid] = v.z;
        st[(k + 3) * 64 + tid] = v.w;
    }
    // Stage weight tile: 32 cols x 128 k.
#pragma unroll
    for (int it = 0; it < 16; it++) {
        int idx = it * 64 + tid;
        int c = idx & 31, k = (idx >> 5) * 4;
        float4 v = *(const float4*)&w[(o0 + c) * DD + k];
        wt[(k + 0) * 32 + c] = v.x;
        wt[(k + 1) * 32 + c] = v.y;
        wt[(k + 2) * 32 + c] = v.z;
        wt[(k + 3) * 32 + c] = v.w;
    }
    __syncthreads();

    const int rg = tid >> 3;       // 0..7
    const int cg = tid & 7;        // 0..7
    const int r0 = rg * 8, c0 = cg * 4;

    float acc[8][4];
#pragma unroll
    for (int r = 0; r < 8; r++)
#pragma unroll
        for (int c = 0; c < 4; c++) acc[r][c] = 0.f;

#pragma unroll 8
    for (int k = 0; k < DD; k++) {
        float4 sa = *(const float4*)&st[k * 64 + r0];
        float4 sb = *(const float4*)&st[k * 64 + r0 + 4];
        float4 w4 = *(const float4*)&wt[k * 32 + c0];
        float sv[8] = {sa.x, sa.y, sa.z, sa.w, sb.x, sb.y, sb.z, sb.w};
        float wv[4] = {w4.x, w4.y, w4.z, w4.w};
#pragma unroll
        for (int r = 0; r < 8; r++)
#pragma unroll
            for (int c = 0; c < 4; c++)
                acc[r][c] += sv[r] * wv[c];
    }

    float bi[4];
#pragma unroll
    for (int c = 0; c < 4; c++) bi[c] = bias[o0 + c0 + c];

    float* dst = (m == 0) ? g_ad : g_bd;
#pragma unroll
    for (int r = 0; r < 8; r++) {
        int n = row0 + r0 + r;
        float4 v = {acc[r][0] + bi[0], acc[r][1] + bi[1],
                    acc[r][2] + bi[2], acc[r][3] + bi[3]};
        *(float4*)&dst[n * DD + o0 + c0] = v;
    }
}

// ---------------------------------------------------------------------------
// Stage 2: heterogeneous grid, 1D 1650 blocks x 128 threads.
//   blocks 0..49    : sv projection (seqs @ W^T + b), hidden under rawtop's
//                     memory-bound phase. sv is post-selection -> grouped-x4
//                     accumulation is safe (1e-3 output tolerance).
//   blocks 50..1649 : rawtop for (b,i) — EXACT R8-passing arithmetic:
//                     lane owns 8 channels, 2 float4 FMA groups, xor-1/xor-2
//                     tree; 2 j's per warp iter (half-split); writer lanes
//                     keep top-3; exact lax.top_k merge (value desc, index
//                     asc) + masked-zero candidates; symmetrized list push.
// ---------------------------------------------------------------------------
__global__ void __launch_bounds__(128) k_rawtop(
    const float* __restrict__ tm,
    const float* __restrict__ seqs,
    const float* __restrict__ w3, const float* __restrict__ b3)
{
    __shared__ float s_seq[32 * DD];     // 16 KB (sv blocks)
    __shared__ float tvs[4][2][HH][3];
    __shared__ int   tjs[4][2][HH][3];

    const int bx = blockIdx.x;
    const int tid = threadIdx.x;

    if (bx < 50) {
        // ---- sv projection block: rows row0..row0+31, all 128 cols ----
        const int row0 = bx * 32;
#pragma unroll
        for (int it = 0; it < 32; it++) {
            int idx = it * 128 + tid;
            int r = idx >> 7, k = idx & 127;
            s_seq[r * DD + k] = seqs[(row0 + r) * DD + k];
        }
        __syncthreads();

        const int o = tid;
        const float bb = b3[o];
        float acc[32];
#pragma unroll
        for (int r = 0; r < 32; r++) acc[r] = 0.f;

        const float4* w4 = (const float4*)(w3 + o * DD);
        for (int k4 = 0; k4 < 32; k4++) {
            float4 wv = w4[k4];
#pragma unroll
            for (int r = 0; r < 32; r++) {
                float4 s4 = *(const float4*)&s_seq[r * DD + k4 * 4];
                acc[r] += s4.x * wv.x + s4.y * wv.y + s4.z * wv.z + s4.w * wv.w;
            }
        }

        const int h = o >> 5, hs = o & 31;
#pragma unroll
        for (int r = 0; r < 32; r++) {
            int n = row0 + r;
            int b_ = n / LL, i_ = n % LL;
            g_sv[((h * BB + b_) * LL + i_) * HS + hs] = acc[r] + bb;
        }
        return;
    }

    // ---- rawtop block ----
    const int bxr = bx - 50;
    const int i = bxr % LL, b = bxr / LL;
    const int w = tid >> 5, lane = tid & 31;
    const int half = lane >> 4;
    const int sub  = lane & 15;
    const int h    = sub >> 2;
    const int d0   = sub * 8;

    const float4* ap = (const float4*)(g_ad + (size_t)(b * LL + i) * DD + d0);
    const float4 aA = ap[0], aB = ap[1];
    float an = aA.x*aA.x + aA.y*aA.y + aA.z*aA.z + aA.w*aA.w
             + aB.x*aB.x + aB.y*aB.y + aB.z*aB.z + aB.w*aB.w;
    an += __shfl_xor_sync(0xffffffffu, an, 1);
    an += __shfl_xor_sync(0xffffffffu, an, 2);
    an = sqrtf(an);

    float v0 = -3.4e38f, v1 = -3.4e38f, v2 = -3.4e38f;
    int   j0 = -1, j1 = -1, j2 = -1;

    const float* tmp = tm   + (size_t)(b * LL + i) * LL * DD + d0;
    const float* bp  = g_bd + (size_t)b * LL * DD + d0;
    float* rr = g_raw + (size_t)((h * BB + b) * LL + i) * LL;

    for (int jb = 2 * w; jb <= i; jb += 16) {
        const int jA = jb + half;
        const int jB = jb + 8 + half;
        const bool pA = (jA <= i);
        const bool pB = (jB <= i);

        float numA = 0.f, denA = 0.f, numB = 0.f, denB = 0.f;

        if (pA) {
            const float4* t4 = (const float4*)(tmp + (size_t)jA * DD);
            const float4* b4 = (const float4*)(bp  + (size_t)jA * DD);
            float4 t0 = t4[0], t1 = t4[1], c0v = b4[0], c1 = b4[1];
            float sx = t0.x + c0v.x, sy = t0.y + c0v.y, sz = t0.z + c0v.z, sw = t0.w + c0v.w;
            numA = aA.x*sx + aA.y*sy + aA.z*sz + aA.w*sw;
            denA = sx*sx + sy*sy + sz*sz + sw*sw;
            sx = t1.x + c1.x; sy = t1.y + c1.y; sz = t1.z + c1.z; sw = t1.w + c1.w;
            numA += aB.x*sx + aB.y*sy + aB.z*sz + aB.w*sw;
            denA += sx*sx + sy*sy + sz*sz + sw*sw;
        }
        if (pB) {
            const float4* t4 = (const float4*)(tmp + (size_t)jB * DD);
            const float4* b4 = (const float4*)(bp  + (size_t)jB * DD);
            float4 t0 = t4[0], t1 = t4[1], c0v = b4[0], c1 = b4[1];
            float sx = t0.x + c0v.x, sy = t0.y + c0v.y, sz = t0.z + c0v.z, sw = t0.w + c0v.w;
            numB = aA.x*sx + aA.y*sy + aA.z*sz + aA.w*sw;
            denB = sx*sx + sy*sy + sz*sz + sw*sw;
            sx = t1.x + c1.x; sy = t1.y + c1.y; sz = t1.z + c1.z; sw = t1.w + c1.w;
            numB += aB.x*sx + aB.y*sy + aB.z*sz + aB.w*sw;
            denB += sx*sx + sy*sy + sz*sz + sw*sw;
        }

        numA += __shfl_xor_sync(0xffffffffu, numA, 1);
        denA += __shfl_xor_sync(0xffffffffu, denA, 1);
        numB += __shfl_xor_sync(0xffffffffu, numB, 1);
        denB += __shfl_xor_sync(0xffffffffu, denB, 1);
        numA += __shfl_xor_sync(0xffffffffu, numA, 2);
        denA += __shfl_xor_sync(0xffffffffu, denA, 2);
        numB += __shfl_xor_sync(0xffffffffu, numB, 2);
        denB += __shfl_xor_sync(0xffffffffu, denB, 2);

        if ((lane & 3) == 0) {
            if (pA) {
                float v = numA / (an * sqrtf(denA) + 1e-6f);
                rr[jA] = v;
                if (v > v0)      { v2=v1; j2=j1; v1=v0; j1=j0; v0=v; j0=jA; }
                else if (v > v1) { v2=v1; j2=j1; v1=v;  j1=jA; }
                else if (v > v2) { v2=v;  j2=jA; }
            }
            if (pB) {
                float v = numB / (an * sqrtf(denB) + 1e-6f);
                rr[jB] = v;
                if (v > v0)      { v2=v1; j2=j1; v1=v0; j1=j0; v0=v; j0=jB; }
                else if (v > v1) { v2=v1; j2=j1; v1=v;  j1=jB; }
                else if (v > v2) { v2=v;  j2=jB; }
            }
        }
    }

    if ((lane & 3) == 0) {
        tvs[w][half][h][0] = v0; tjs[w][half][h][0] = j0;
        tvs[w][half][h][1] = v1; tjs[w][half][h][1] = j1;
        tvs[w][half][h][2] = v2; tjs[w][half][h][2] = j2;
    }
    __syncthreads();

    // merge + list push: thread hh < 4 handles head hh
    if (tid < HH) {
        const int hh = tid;
        float V0 = -3.4e38f, V1 = -3.4e38f, V2 = -3.4e38f;
        int   I0 = 0x7fffffff, I1 = 0x7fffffff, I2 = 0x7fffffff;
        auto ins = [&](float v, int j) {
            if (j < 0) return;
            if (v > V0 || (v == V0 && j < I0)) { V2=V1;I2=I1; V1=V0;I1=I0; V0=v;I0=j; }
            else if (v > V1 || (v == V1 && j < I1)) { V2=V1;I2=I1; V1=v;I1=j; }
            else if (v > V2 || (v == V2 && j < I2)) { V2=v;I2=j; }
        };
#pragma unroll
        for (int ww = 0; ww < 4; ww++)
#pragma unroll
            for (int hf = 0; hf < 2; hf++)
#pragma unroll
                for (int qq = 0; qq < 3; qq++)
                    ins(tvs[ww][hf][hh][qq], tjs[ww][hf][hh][qq]);
#pragma unroll
        for (int z = 1; z <= 3; z++) {
            int jz = i + z;
            if (jz < LL) ins(0.0f, jz);   // masked zeros (index-asc ties)
        }
        const int bh = hh * BB + b;
        const int rg = bh * LL + i;
        int sel[3] = {I0, I1, I2};
#pragma unroll
        for (int s = 0; s < 3; s++) {
            int t = sel[s];
            if (t <= i) {
                int p = atomicAdd(&g_cnt[rg], 1);
                if (p < CAP) g_list[rg * CAP + p] = t;
            } else {
                int tg = bh * LL + t;
                int p = atomicAdd(&g_cnt[tg], 1);
                if (p < CAP) g_list[tg * CAP + p] = i;
            }
        }
    }
}

// ---------------------------------------------------------------------------
// Stage 3 (fused sparse gather + LayerNorm): block per (b,i), warp = head.
// Bitmask dedup; paired bit extraction for MLP; ascending-j (deterministic).
// ---------------------------------------------------------------------------
__global__ void k_gather_ln(const float* __restrict__ tm,
                            const float* __restrict__ gam,
                            const float* __restrict__ bet,
                            float* __restrict__ out_ln,
                            float* __restrict__ out_tio)
{
    const int i = blockIdx.x, b = blockIdx.y;
    const int tid = threadIdx.x;
    const int h = tid >> 5, lane = tid & 31;
    const int bh = h * BB + b;
    const int rg = bh * LL + i;

    __shared__ unsigned bm[HH][7];
    __shared__ float red[4];

    if (lane < 7) bm[h][lane] = 0u;
    __syncwarp();

    const int n = min(g_cnt[rg], CAP);
    for (int c = lane; c < n; c += 32) {
        int j = g_list[rg * CAP + c];
        atomicOr(&bm[h][j >> 5], 1u << (j & 31));
    }
    __syncwarp();

    float ao = 0.f, at = 0.f;
    float ao2 = 0.f, at2 = 0.f;
    const float* rrow = g_raw + (size_t)rg * LL;
    const float* tmb  = tm + (size_t)(b * LL + i) * LL * DD + h * HS + lane;
    const float* svb  = g_sv + (size_t)bh * LL * HS + lane;

    for (int w = 0; w < 7; w++) {
        unsigned m = bm[h][w];
        while (m) {
            int b1 = __ffs(m) - 1;  m &= m - 1;
            int b2 = -1;
            if (m) { b2 = __ffs(m) - 1; m &= m - 1; }
            int ja = w * 32 + b1;
            float sga = rrow[ja];
            float sv_a = svb[ja * HS];
            float tm_a = tmb[(size_t)ja * DD];
            if (b2 >= 0) {
                int jb2 = w * 32 + b2;
                float sgb = rrow[jb2];
                ao2 += sgb * svb[jb2 * HS];
                at2 += sgb * tmb[(size_t)jb2 * DD];
            }
            ao += sga * sv_a;
            at += sga * tm_a;
        }
    }
    ao += ao2;
    at += at2;

    const int d = tid;                 // d = h*HS + lane
    out_tio[(b * LL + i) * DD + d] = at;

    // LayerNorm over the 128 'ao' values
    float s = ao;
#pragma unroll
    for (int k = 16; k; k >>= 1) s += __shfl_xor_sync(0xffffffffu, s, k);
    if (lane == 0) red[h] = s;
    __syncthreads();
    float mu = (red[0] + red[1] + red[2] + red[3]) * (1.f / 128.f);
    __syncthreads();

    float dv = ao - mu;
    float s2 = dv * dv;
#pragma unroll
    for (int k = 16; k; k >>= 1) s2 += __shfl_xor_sync(0xffffffffu, s2, k);
    if (lane == 0) red[h] = s2;
    __syncthreads();
    float var = (red[0] + red[1] + red[2] + red[3]) * (1.f / 128.f);

    out_ln[(b * LL + i) * DD + d] = dv / sqrtf(var + 1e-8f) * gam[d] + bet[d];
}

// ---------------------------------------------------------------------------
extern "C" void kernel_launch(void* const* d_in, const int* in_sizes, int n_in,
                              void* d_out, int out_size)
{
    const float* seqs = (const float*)d_in[0];
    // d_in[1] = attention_mask (known causal triu) — unused
    const float* tm   = (const float*)d_in[2];
    const float* w1   = (const float*)d_in[3];
    const float* b1   = (const float*)d_in[4];
    const float* w2   = (const float*)d_in[5];
    const float* b2   = (const float*)d_in[6];
    const float* w3   = (const float*)d_in[7];
    const float* b3   = (const float*)d_in[8];
    const float* lng  = (const float*)d_in[9];
    const float* lnb  = (const float*)d_in[10];

    float* out_ln  = (float*)d_out;
    float* out_tio = out_ln + BB * LL * DD;

    k_gemm     <<<dim3(25, 8),  64>>>(seqs, w1, b1, w2, b2);
    k_rawtop   <<<1650,        128>>>(tm, seqs, w3, b3);
    k_gather_ln<<<dim3(LL, BB),128>>>(tm, lng, lnb, out_ln, out_tio);
}

// round 13
// speedup vs baseline: 1.1393x; 1.0466x over previous
#include <cuda_runtime.h>
#include <cstdint>

// Problem constants
#define BB   8
#define LL   200
#define DD   128
#define HH   4
#define HS   32
#define HB   (HH*BB)        // 32
#define NROW (HB*LL)        // 6400
#define CAP  204

// Scratch (device globals; no allocation allowed)
__device__ float g_ad[BB*LL*DD];       // a in [b][i][d]
__device__ float g_bd[BB*LL*DD];       // b in [b][j][d]
__device__ float g_sv[HB*LL*HS];       // sv in [bh][j][hs]
__device__ float g_raw[NROW*LL];       // only j<=i valid
__device__ int   g_cnt[NROW];
__device__ int   g_list[NROW*CAP];

// ---------------------------------------------------------------------------
// Stage 1: a/b projections (sv lives in k_rawtop's grid).
// grid (50 rowtiles of 32, 8 = 2 matrices x 4 coltiles of 32), block 64
// -> 400 blocks (5.4 warps/SM, 2x R11's parallelism).
// Tile 32x32, 4x4 per thread; full-K XOR-swizzled smem; conflict-free
// STS (lane = row) and LDS.128. Per-output FMA order = serial k,
// BIT-IDENTICAL to the R8/R11-passing versions. Also zeroes g_cnt.
// ---------------------------------------------------------------------------
__global__ void __launch_bounds__(64) k_gemm(
                       const float* __restrict__ seqs,
                       const float* __restrict__ w1, const float* __restrict__ b1,
                       const float* __restrict__ w2, const float* __restrict__ b2)
{
    __shared__ float st[128 * 32];   // [k][r swizzled] 16 KB
    __shared__ float wt[128 * 32];   // [k][c swizzled] 16 KB

    const int ct = blockIdx.y;
    const int m  = ct >> 2;                 // matrix 0..1
    const int o0 = (ct & 3) * 32;           // col base within matrix
    const float* w    = (m == 0) ? w1 : w2;
    const float* bias = (m == 0) ? b1 : b2;

    const int row0 = blockIdx.x * 32;
    const int tid  = threadIdx.x;

    {
        int idx = (blockIdx.y * 50 + blockIdx.x) * 64 + tid;
        if (idx < NROW) g_cnt[idx] = 0;
    }

    // Stage seqs tile: lane owns row r = idx&31 -> conflict-free STS.
#pragma unroll
    for (int it = 0; it < 16; it++) {
        int idx = it * 64 + tid;
        int r = idx & 31, k = (idx >> 5) * 4;
        float4 v = *(const float4*)&seqs[(row0 + r) * DD + k];
        st[(k + 0) * 32 + (r ^ (((k + 0) & 7) << 2))] = v.x;
        st[(k + 1) * 32 + (r ^ (((k + 1) & 7) << 2))] = v.y;
        st[(k + 2) * 32 + (r ^ (((k + 2) & 7) << 2))] = v.z;
        st[(k + 3) * 32 + (r ^ (((k + 3) & 7) << 2))] = v.w;
    }
#pragma unroll
    for (int it = 0; it < 16; it++) {
        int idx = it * 64 + tid;
        int c = idx & 31, k = (idx >> 5) * 4;
        float4 v = *(const float4*)&w[(o0 + c) * DD + k];
        wt[(k + 0) * 32 + (c ^ (((k + 0) & 7) << 2))] = v.x;
        wt[(k + 1) * 32 + (c ^ (((k + 1) & 7) << 2))] = v.y;
        wt[(k + 2) * 32 + (c ^ (((k + 2) & 7) << 2))] = v.z;
        wt[(k + 3) * 32 + (c ^ (((k + 3) & 7) << 2))] = v.w;
    }
    __syncthreads();

    const int rg = tid >> 3;       // 0..7
    const int cg = tid & 7;        // 0..7
    const int r0 = rg * 4, c0 = cg * 4;

    float acc[4][4];
#pragma unroll
    for (int r = 0; r < 4; r++)
#pragma unroll
        for (int c = 0; c < 4; c++) acc[r][c] = 0.f;

#pragma unroll 8
    for (int k = 0; k < DD; k++) {
        const int sw = (k & 7) << 2;
        float4 s4 = *(const float4*)&st[k * 32 + (r0 ^ sw)];
        float4 w4 = *(const float4*)&wt[k * 32 + (c0 ^ sw)];
        float sv[4] = {s4.x, s4.y, s4.z, s4.w};
        float wv[4] = {w4.x, w4.y, w4.z, w4.w};
#pragma unroll
        for (int r = 0; r < 4; r++)
#pragma unroll
            for (int c = 0; c < 4; c++)
                acc[r][c] += sv[r] * wv[c];
    }

    float bi[4];
#pragma unroll
    for (int c = 0; c < 4; c++) bi[c] = bias[o0 + c0 + c];

    float* dst = (m == 0) ? g_ad : g_bd;
#pragma unroll
    for (int r = 0; r < 4; r++) {
        int n = row0 + r0 + r;
        float4 v = {acc[r][0] + bi[0], acc[r][1] + bi[1],
                    acc[r][2] + bi[2], acc[r][3] + bi[3]};
        *(float4*)&dst[n * DD + o0 + c0] = v;
    }
}

// ---------------------------------------------------------------------------
// Stage 2: heterogeneous grid, 1D 1650 blocks x 128 threads.
//   blocks 0..49    : sv projection (hidden under rawtop's memory phase).
//   blocks 50..1649 : rawtop for (b,i), i = (29*bx2) mod 200 — coprime
//                     scramble so same-SM blocks (bid stride ~148) alternate
//                     heavy/light i (29*148 = 92 mod 200). Pure permutation:
//                     per-(i,j) arithmetic identical; bitmask dedup in
//                     gather canonicalizes list order; CAP never overflows.
//                     tm loads use __ldcs (streaming, read-once).
//                     EXACT R8-passing arithmetic per (i,j).
// ---------------------------------------------------------------------------
__global__ void __launch_bounds__(128) k_rawtop(
    const float* __restrict__ tm,
    const float* __restrict__ seqs,
    const float* __restrict__ w3, const float* __restrict__ b3)
{
    __shared__ float s_seq[32 * DD];     // 16 KB (sv blocks)
    __shared__ float tvs[4][2][HH][3];
    __shared__ int   tjs[4][2][HH][3];

    const int bx = blockIdx.x;
    const int tid = threadIdx.x;

    if (bx < 50) {
        // ---- sv projection block: rows row0..row0+31, all 128 cols ----
        const int row0 = bx * 32;
#pragma unroll
        for (int it = 0; it < 32; it++) {
            int idx = it * 128 + tid;
            int r = idx >> 7, k = idx & 127;
            s_seq[r * DD + k] = seqs[(row0 + r) * DD + k];
        }
        __syncthreads();

        const int o = tid;
        const float bb = b3[o];
        float acc[32];
#pragma unroll
        for (int r = 0; r < 32; r++) acc[r] = 0.f;

        const float4* w4 = (const float4*)(w3 + o * DD);
        for (int k4 = 0; k4 < 32; k4++) {
            float4 wv = w4[k4];
#pragma unroll
            for (int r = 0; r < 32; r++) {
                float4 s4 = *(const float4*)&s_seq[r * DD + k4 * 4];
                acc[r] += s4.x * wv.x + s4.y * wv.y + s4.z * wv.z + s4.w * wv.w;
            }
        }

        const int h = o >> 5, hs = o & 31;
#pragma unroll
        for (int r = 0; r < 32; r++) {
            int n = row0 + r;
            int b_ = n / LL, i_ = n % LL;
            g_sv[((h * BB + b_) * LL + i_) * HS + hs] = acc[r] + bb;
        }
        return;
    }

    // ---- rawtop block ----
    const int bxr = bx - 50;
    const int b   = bxr / LL;
    const int bx2 = bxr % LL;
    const int i   = (29 * bx2) % LL;    // load-balance scramble
    const int w = tid >> 5, lane = tid & 31;
    const int half = lane >> 4;
    const int sub  = lane & 15;
    const int h    = sub >> 2;
    const int d0   = sub * 8;

    const float4* ap = (const float4*)(g_ad + (size_t)(b * LL + i) * DD + d0);
    const float4 aA = ap[0], aB = ap[1];
    float an = aA.x*aA.x + aA.y*aA.y + aA.z*aA.z + aA.w*aA.w
             + aB.x*aB.x + aB.y*aB.y + aB.z*aB.z + aB.w*aB.w;
    an += __shfl_xor_sync(0xffffffffu, an, 1);
    an += __shfl_xor_sync(0xffffffffu, an, 2);
    an = sqrtf(an);

    float v0 = -3.4e38f, v1 = -3.4e38f, v2 = -3.4e38f;
    int   j0 = -1, j1 = -1, j2 = -1;

    const float* tmp = tm   + (size_t)(b * LL + i) * LL * DD + d0;
    const float* bp  = g_bd + (size_t)b * LL * DD + d0;
    float* rr = g_raw + (size_t)((h * BB + b) * LL + i) * LL;

    for (int jb = 2 * w; jb <= i; jb += 16) {
        const int jA = jb + half;
        const int jB = jb + 8 + half;
        const bool pA = (jA <= i);
        const bool pB = (jB <= i);

        float numA = 0.f, denA = 0.f, numB = 0.f, denB = 0.f;

        if (pA) {
            const float4* t4 = (const float4*)(tmp + (size_t)jA * DD);
            const float4* b4 = (const float4*)(bp  + (size_t)jA * DD);
            float4 t0 = __ldcs(t4), t1 = __ldcs(t4 + 1);
            float4 c0v = b4[0], c1 = b4[1];
            float sx = t0.x + c0v.x, sy = t0.y + c0v.y, sz = t0.z + c0v.z, sw = t0.w + c0v.w;
            numA = aA.x*sx + aA.y*sy + aA.z*sz + aA.w*sw;
            denA = sx*sx + sy*sy + sz*sz + sw*sw;
            sx = t1.x + c1.x; sy = t1.y + c1.y; sz = t1.z + c1.z; sw = t1.w + c1.w;
            numA += aB.x*sx + aB.y*sy + aB.z*sz + aB.w*sw;
            denA += sx*sx + sy*sy + sz*sz + sw*sw;
        }
        if (pB) {
            const float4* t4 = (const float4*)(tmp + (size_t)jB * DD);
            const float4* b4 = (const float4*)(bp  + (size_t)jB * DD);
            float4 t0 = __ldcs(t4), t1 = __ldcs(t4 + 1);
            float4 c0v = b4[0], c1 = b4[1];
            float sx = t0.x + c0v.x, sy = t0.y + c0v.y, sz = t0.z + c0v.z, sw = t0.w + c0v.w;
            numB = aA.x*sx + aA.y*sy + aA.z*sz + aA.w*sw;
            denB = sx*sx + sy*sy + sz*sz + sw*sw;
            sx = t1.x + c1.x; sy = t1.y + c1.y; sz = t1.z + c1.z; sw = t1.w + c1.w;
            numB += aB.x*sx + aB.y*sy + aB.z*sz + aB.w*sw;
            denB += sx*sx + sy*sy + sz*sz + sw*sw;
        }

        numA += __shfl_xor_sync(0xffffffffu, numA, 1);
        denA += __shfl_xor_sync(0xffffffffu, denA, 1);
        numB += __shfl_xor_sync(0xffffffffu, numB, 1);
        denB += __shfl_xor_sync(0xffffffffu, denB, 1);
        numA += __shfl_xor_sync(0xffffffffu, numA, 2);
        denA += __shfl_xor_sync(0xffffffffu, denA, 2);
        numB += __shfl_xor_sync(0xffffffffu, numB, 2);
        denB += __shfl_xor_sync(0xffffffffu, denB, 2);

        if ((lane & 3) == 0) {
            if (pA) {
                float v = numA / (an * sqrtf(denA) + 1e-6f);
                rr[jA] = v;
                if (v > v0)      { v2=v1; j2=j1; v1=v0; j1=j0; v0=v; j0=jA; }
                else if (v > v1) { v2=v1; j2=j1; v1=v;  j1=jA; }
                else if (v > v2) { v2=v;  j2=jA; }
            }
            if (pB) {
                float v = numB / (an * sqrtf(denB) + 1e-6f);
                rr[jB] = v;
                if (v > v0)      { v2=v1; j2=j1; v1=v0; j1=j0; v0=v; j0=jB; }
                else if (v > v1) { v2=v1; j2=j1; v1=v;  j1=jB; }
                else if (v > v2) { v2=v;  j2=jB; }
            }
        }
    }

    if ((lane & 3) == 0) {
        tvs[w][half][h][0] = v0; tjs[w][half][h][0] = j0;
        tvs[w][half][h][1] = v1; tjs[w][half][h][1] = j1;
        tvs[w][half][h][2] = v2; tjs[w][half][h][2] = j2;
    }
    __syncthreads();

    // merge + list push: thread hh < 4 handles head hh
    if (tid < HH) {
        const int hh = tid;
        float V0 = -3.4e38f, V1 = -3.4e38f, V2 = -3.4e38f;
        int   I0 = 0x7fffffff, I1 = 0x7fffffff, I2 = 0x7fffffff;
        auto ins = [&](float v, int j) {
            if (j < 0) return;
            if (v > V0 || (v == V0 && j < I0)) { V2=V1;I2=I1; V1=V0;I1=I0; V0=v;I0=j; }
            else if (v > V1 || (v == V1 && j < I1)) { V2=V1;I2=I1; V1=v;I1=j; }
            else if (v > V2 || (v == V2 && j < I2)) { V2=v;I2=j; }
        };
#pragma unroll
        for (int ww = 0; ww < 4; ww++)
#pragma unroll
            for (int hf = 0; hf < 2; hf++)
#pragma unroll
                for (int qq = 0; qq < 3; qq++)
                    ins(tvs[ww][hf][hh][qq], tjs[ww][hf][hh][qq]);
#pragma unroll
        for (int z = 1; z <= 3; z++) {
            int jz = i + z;
            if (jz < LL) ins(0.0f, jz);   // masked zeros (index-asc ties)
        }
        const int bh = hh * BB + b;
        const int rg = bh * LL + i;
        int sel[3] = {I0, I1, I2};
#pragma unroll
        for (int s = 0; s < 3; s++) {
            int t = sel[s];
            if (t <= i) {
                int p = atomicAdd(&g_cnt[rg], 1);
                if (p < CAP) g_list[rg * CAP + p] = t;
            } else {
                int tg = bh * LL + t;
                int p = atomicAdd(&g_cnt[tg], 1);
                if (p < CAP) g_list[tg * CAP + p] = i;
            }
        }
    }
}

// ---------------------------------------------------------------------------
// Stage 3 (fused sparse gather + LayerNorm): block per (b,i), warp = head.
// Bitmask dedup; paired bit extraction for MLP; ascending-j (deterministic).
// ---------------------------------------------------------------------------
__global__ void k_gather_ln(const float* __restrict__ tm,
                            const float* __restrict__ gam,
                            const float* __restrict__ bet,
                            float* __restrict__ out_ln,
                            float* __restrict__ out_tio)
{
    const int i = blockIdx.x, b = blockIdx.y;
    const int tid = threadIdx.x;
    const int h = tid >> 5, lane = tid & 31;
    const int bh = h * BB + b;
    const int rg = bh * LL + i;

    __shared__ unsigned bm[HH][7];
    __shared__ float red[4];

    if (lane < 7) bm[h][lane] = 0u;
    __syncwarp();

    const int n = min(g_cnt[rg], CAP);
    for (int c = lane; c < n; c += 32) {
        int j = g_list[rg * CAP + c];
        atomicOr(&bm[h][j >> 5], 1u << (j & 31));
    }
    __syncwarp();

    float ao = 0.f, at = 0.f;
    float ao2 = 0.f, at2 = 0.f;
    const float* rrow = g_raw + (size_t)rg * LL;
    const float* tmb  = tm + (size_t)(b * LL + i) * LL * DD + h * HS + lane;
    const float* svb  = g_sv + (size_t)bh * LL * HS + lane;

    for (int w = 0; w < 7; w++) {
        unsigned m = bm[h][w];
        while (m) {
            int b1 = __ffs(m) - 1;  m &= m - 1;
            int b2 = -1;
            if (m) { b2 = __ffs(m) - 1; m &= m - 1; }
            int ja = w * 32 + b1;
            float sga = rrow[ja];
            float sv_a = svb[ja * HS];
            float tm_a = tmb[(size_t)ja * DD];
            if (b2 >= 0) {
                int jb2 = w * 32 + b2;
                float sgb = rrow[jb2];
                ao2 += sgb * svb[jb2 * HS];
                at2 += sgb * tmb[(size_t)jb2 * DD];
            }
            ao += sga * sv_a;
            at += sga * tm_a;
        }
    }
    ao += ao2;
    at += at2;

    const int d = tid;                 // d = h*HS + lane
    out_tio[(b * LL + i) * DD + d] = at;

    // LayerNorm over the 128 'ao' values
    float s = ao;
#pragma unroll
    for (int k = 16; k; k >>= 1) s += __shfl_xor_sync(0xffffffffu, s, k);
    if (lane == 0) red[h] = s;
    __syncthreads();
    float mu = (red[0] + red[1] + red[2] + red[3]) * (1.f / 128.f);
    __syncthreads();

    float dv = ao - mu;
    float s2 = dv * dv;
#pragma unroll
    for (int k = 16; k; k >>= 1) s2 += __shfl_xor_sync(0xffffffffu, s2, k);
    if (lane == 0) red[h] = s2;
    __syncthreads();
    float var = (red[0] + red[1] + red[2] + red[3]) * (1.f / 128.f);

    out_ln[(b * LL + i) * DD + d] = dv / sqrtf(var + 1e-8f) * gam[d] + bet[d];
}

// ---------------------------------------------------------------------------
extern "C" void kernel_launch(void* const* d_in, const int* in_sizes, int n_in,
                              void* d_out, int out_size)
{
    const float* seqs = (const float*)d_in[0];
    // d_in[1] = attention_mask (known causal triu) — unused
    const float* tm   = (const float*)d_in[2];
    const float* w1   = (const float*)d_in[3];
    const float* b1   = (const float*)d_in[4];
    const float* w2   = (const float*)d_in[5];
    const float* b2   = (const float*)d_in[6];
    const float* w3   = (const float*)d_in[7];
    const float* b3   = (const float*)d_in[8];
    const float* lng  = (const float*)d_in[9];
    const float* lnb  = (const float*)d_in[10];

    float* out_ln  = (float*)d_out;
    float* out_tio = out_ln + BB * LL * DD;

    k_gemm     <<<dim3(50, 8),  64>>>(seqs, w1, b1, w2, b2);
    k_rawtop   <<<1650,        128>>>(tm, seqs, w3, b3);
    k_gather_ln<<<dim3(LL, BB),128>>>(tm, lng, lnb, out_ln, out_tio);
}